// round 3
// baseline (speedup 1.0000x reference)
#include <cuda_runtime.h>
#include <math.h>

// Problem constants
// B=2, C=32, H=512, W=512, SCALE=2 -> Hs=Ws=256, S2=4

// ---------------- scratch (__device__ globals; no allocation allowed) ----------------
__device__ float         d_Fpart[2 * 8 * 8];        // [b][hblk][t*2+reim]
__device__ float2        d_F[2 * 4];                // F[b][t]
__device__ float         d_TR[2 * 32 * 4 * 4];      // MLP-real table [b][g][o][k]
__device__ float         d_TI[2 * 32 * 4 * 4];      // MLP-imag table
__device__ float2        d_Cn[2 * 32 * 256];        // combined freq value per (b,c,byte-id)
__device__ unsigned char d_pix[256 * 256];          // per-pixel byte id
__device__ float2        d_tw[128];                 // exp(+2*pi*i*t/256), t<128
__device__ float2        d_Y[2 * 32 * 256 * 256];   // row-IFFT intermediate (33.5 MB)

// ---------------- K0: partial sums for F[b,t] over 64-row slabs ----------------
__global__ void k0_colpart(const float* __restrict__ x) {
    int b = blockIdx.y;
    int hb = blockIdx.x;          // 0..7, 64 rows each
    int w = threadIdx.x;          // 512 threads, one column each
    const float* xp = x + (size_t)b * 32 * 512 * 512 + (size_t)(hb * 64) * 512 + w;
    float s = 0.f;
#pragma unroll 8
    for (int h = 0; h < 64; h++) s += xp[(size_t)h * 512];

    float vals[8];
#pragma unroll
    for (int t = 0; t < 4; t++) {
        // e^{-i*2*pi*t*w/512}: angle/pi = t*w/256
        float ph = (float)(t * w) * (1.0f / 256.0f);
        float sn, cs;
        sincospif(ph, &sn, &cs);
        vals[2 * t] = s * cs;
        vals[2 * t + 1] = -s * sn;
    }
    unsigned lane = threadIdx.x & 31, wid = threadIdx.x >> 5;
#pragma unroll
    for (int v = 0; v < 8; v++)
#pragma unroll
        for (int off = 16; off; off >>= 1)
            vals[v] += __shfl_down_sync(0xffffffff, vals[v], off);

    __shared__ float wsum[16][8];
    if (lane == 0)
        for (int v = 0; v < 8; v++) wsum[wid][v] = vals[v];
    __syncthreads();
    if (threadIdx.x == 0) {
        for (int v = 0; v < 8; v++) {
            float a = 0.f;
            for (int k = 0; k < 16; k++) a += wsum[k][v];
            d_Fpart[(b * 8 + hb) * 8 + v] = a;
        }
    }
}

// ---------------- K1: reduce F, build MLP output tables TR/TI ----------------
__global__ void k1_tables(const float* __restrict__ w1r, const float* __restrict__ b1r,
                          const float* __restrict__ w2r, const float* __restrict__ b2r,
                          const float* __restrict__ w1i, const float* __restrict__ b1i,
                          const float* __restrict__ w2i, const float* __restrict__ b2i) {
    __shared__ float2 sF[8];
    int tid = threadIdx.x;
    if (tid < 8) {
        int b = tid >> 2, k = tid & 3;
        float re = 0.f, im = 0.f;
        for (int hb = 0; hb < 8; hb++) {
            re += d_Fpart[(b * 8 + hb) * 8 + 2 * k];
            im += d_Fpart[(b * 8 + hb) * 8 + 2 * k + 1];
        }
        sF[tid] = make_float2(re, im);
        d_F[tid] = sF[tid];
    }
    __syncthreads();

    // 2048 entries: [isImag][b][g][o][k]
    for (int e = tid; e < 2048; e += 256) {
        int isI = e >> 10;
        int r = e & 1023;
        int b = r >> 9;
        int g = (r >> 4) & 31;
        int o = (r >> 2) & 3;
        int k = r & 3;
        const float* w1 = isI ? w1i : w1r;
        const float* b1 = isI ? b1i : b1r;
        const float* w2 = isI ? w2i : w2r;
        const float* b2 = isI ? b2i : b2r;
        float v = isI ? sF[b * 4 + k].y : sF[b * 4 + k].x;
        float h[4];
#pragma unroll
        for (int ii = 0; ii < 4; ii++) {
            const float* wrow = w1 + (g * 4 + ii) * 4;
            float ws = wrow[0] + wrow[1] + wrow[2] + wrow[3];
            float y = v * ws + b1[g * 4 + ii];
            h[ii] = y > 0.f ? y : 0.1f * y;   // LeakyReLU(0.1)
        }
        float out = b2[g * 4 + o];
#pragma unroll
        for (int ii = 0; ii < 4; ii++) out += w2[(g * 4 + o) * 4 + ii] * h[ii];
        (isI ? d_TI : d_TR)[((b * 32 + g) * 4 + o) * 4 + k] = out;
    }
}

// ---------------- K2: combined softmax-weighted freq values per byte-id ----------------
__global__ void k2_cn() {
    int bc = blockIdx.x;              // 0..63
    int b = bc >> 5, Cc = bc & 31;
    __shared__ float swr[4][4], swi[4][4];
    __shared__ float2 sFv[4];
    int tid = threadIdx.x;            // 256 threads, one byte-id each
    if (tid < 32) {
        int P = tid >> 3, kk = (tid >> 1) & 3, ri = tid & 1;
        int g = 8 * P + (Cc >> 2), o = Cc & 3;
        float v = (ri ? d_TI : d_TR)[((b * 32 + g) * 4 + o) * 4 + kk];
        if (ri) swi[P][kk] = v; else swr[P][kk] = v;
    } else if (tid < 36) {
        sFv[tid - 32] = d_F[b * 4 + (tid - 32)];
    }
    __syncthreads();

    int id = tid;
    int ks[4] = { id & 3, (id >> 2) & 3, (id >> 4) & 3, (id >> 6) & 3 };
    float ar[4], ai[4];
#pragma unroll
    for (int P = 0; P < 4; P++) { ar[P] = swr[P][ks[P]]; ai[P] = swi[P][ks[P]]; }

    float mr = fmaxf(fmaxf(ar[0], ar[1]), fmaxf(ar[2], ar[3]));
    float mi = fmaxf(fmaxf(ai[0], ai[1]), fmaxf(ai[2], ai[3]));
    float er[4], ei_[4], sre = 0.f, sie = 0.f;
#pragma unroll
    for (int P = 0; P < 4; P++) {
        er[P] = __expf(ar[P] - mr); sre += er[P];
        ei_[P] = __expf(ai[P] - mi); sie += ei_[P];
    }
    float rinv = 1.f / sre, iinv = 1.f / sie;
    float Cr = 0.f, Ci = 0.f;
#pragma unroll
    for (int P = 0; P < 4; P++) {
        float sr = er[P] * rinv, si = ei_[P] * iinv;
        float fr = sFv[ks[P]].x, fi = sFv[ks[P]].y;
        Cr += fr * sr - fi * si;
        Ci += fr * si + fi * sr;
    }
    // fold ifft2 1/(256*256) normalization
    d_Cn[bc * 256 + id] = make_float2(Cr * (1.f / 65536.f), Ci * (1.f / 65536.f));
}

// ---------------- K3: per-pixel permutation byte id ----------------
__global__ void k3_pix(const int* __restrict__ ei) {
    int pix = blockIdx.x * 256 + threadIdx.x;   // grid 256 x 256 threads = 65536
    unsigned v = 0;
#pragma unroll
    for (int P = 0; P < 4; P++)
        v |= ((unsigned)ei[(size_t)P * 2097152 + pix] & 3u) << (2 * P);
    d_pix[pix] = (unsigned char)v;
}

// ---------------- K4: inverse-FFT twiddles exp(+2*pi*i*t/256) ----------------
__global__ void k4_tw() {
    int t = threadIdx.x;   // 128
    float sn, cs;
    sincospif((float)t * (1.0f / 128.0f), &sn, &cs);
    d_tw[t] = make_float2(cs, sn);
}

// ---------------- K5: row IFFT (length 256, Stockham radix-2 DIF, inverse) ----------------
__global__ void k5_row() {
    __shared__ float2 sCn[256];
    __shared__ float2 bufA[256], bufB[256];
    __shared__ float2 tw[128];
    int bc = blockIdx.x >> 8;
    int i = blockIdx.x & 255;
    int t = threadIdx.x;   // 128

    sCn[t] = d_Cn[bc * 256 + t];
    sCn[t + 128] = d_Cn[bc * 256 + t + 128];
    tw[t] = d_tw[t];
    __syncthreads();

    bufA[t] = sCn[d_pix[i * 256 + t]];
    bufA[t + 128] = sCn[d_pix[i * 256 + t + 128]];
    __syncthreads();

    float2* A = bufA;
    float2* Bf = bufB;
#pragma unroll
    for (int s = 0; s < 8; s++) {
        int m1 = (1 << s) - 1;
        int k = t & m1;
        int jm = t - k;               // j*m
        float2 c0 = A[t];
        float2 c1 = A[t + 128];
        float2 w = tw[jm];
        float dr = c0.x - c1.x, di = c0.y - c1.y;
        int lo = 2 * jm + k;
        Bf[lo] = make_float2(c0.x + c1.x, c0.y + c1.y);
        Bf[lo + m1 + 1] = make_float2(w.x * dr - w.y * di, w.x * di + w.y * dr);
        __syncthreads();
        float2* tmp = A; A = Bf; Bf = tmp;
    }
    // result in bufA (== A after 8 swaps), natural order
    size_t base = (size_t)bc * 65536 + (size_t)i * 256;
    d_Y[base + t] = A[t];
    d_Y[base + t + 128] = A[t + 128];
}

// ---------------- K6: column IFFT + |.| + fused 2x2 avg-pool add ----------------
__global__ void k6_col(const float* __restrict__ x, float* __restrict__ out) {
    __shared__ float2 tA[8 * 257];
    __shared__ float2 tB[8 * 257];
    __shared__ float2 tw[128];
    int bc = blockIdx.x >> 5;
    int jt = blockIdx.x & 31;
    int j0 = jt * 8;
    int t = threadIdx.x;            // 256
    if (t < 128) tw[t] = d_tw[t];
    int c = t & 7;
    int ib = t >> 3;                // 0..31
    size_t ybase = (size_t)bc * 65536;

#pragma unroll
    for (int r = 0; r < 8; r++) {
        int i = ib + r * 32;
        tA[c * 257 + i] = d_Y[ybase + (size_t)i * 256 + j0 + c];
    }
    __syncthreads();

    float2* A = tA;
    float2* Bf = tB;
#pragma unroll
    for (int s = 0; s < 8; s++) {
        int m1 = (1 << s) - 1;
#pragma unroll
        for (int u = 0; u < 4; u++) {
            int bf = t + u * 256;           // 0..1023
            int col = bf >> 7;              // 0..7
            int tt = bf & 127;
            int k = tt & m1;
            int jm = tt - k;
            float2 c0 = A[col * 257 + tt];
            float2 c1 = A[col * 257 + tt + 128];
            float2 w = tw[jm];
            float dr = c0.x - c1.x, di = c0.y - c1.y;
            int lo = 2 * jm + k;
            Bf[col * 257 + lo] = make_float2(c0.x + c1.x, c0.y + c1.y);
            Bf[col * 257 + lo + m1 + 1] =
                make_float2(w.x * dr - w.y * di, w.x * di + w.y * dr);
        }
        __syncthreads();
        float2* tmp = A; A = Bf; Bf = tmp;
    }
    // result in tA; epilogue: magnitude + 2x2 average pool of x
    size_t xbase = (size_t)bc * 262144;   // (b*32+c)*512*512
    size_t obase = (size_t)bc * 65536;
#pragma unroll
    for (int r = 0; r < 8; r++) {
        int i = ib + r * 32;
        int j = j0 + c;
        float2 v = A[c * 257 + i];
        float mag = sqrtf(v.x * v.x + v.y * v.y);
        const float2 a0 = *(const float2*)(x + xbase + (size_t)(2 * i) * 512 + 2 * j);
        const float2 a1 = *(const float2*)(x + xbase + (size_t)(2 * i + 1) * 512 + 2 * j);
        out[obase + (size_t)i * 256 + j] = mag + 0.25f * (a0.x + a0.y + a1.x + a1.y);
    }
}

// ---------------- launch ----------------
extern "C" void kernel_launch(void* const* d_in, const int* in_sizes, int n_in,
                              void* d_out, int out_size) {
    const float* x   = (const float*)d_in[0];
    const int*   ei  = (const int*)d_in[1];
    const float* w1r = (const float*)d_in[2];
    const float* b1r = (const float*)d_in[3];
    const float* w2r = (const float*)d_in[4];
    const float* b2r = (const float*)d_in[5];
    const float* w1i = (const float*)d_in[6];
    const float* b1i = (const float*)d_in[7];
    const float* w2i = (const float*)d_in[8];
    const float* b2i = (const float*)d_in[9];
    float* out = (float*)d_out;

    k0_colpart<<<dim3(8, 2), 512>>>(x);
    k1_tables<<<1, 256>>>(w1r, b1r, w2r, b2r, w1i, b1i, w2i, b2i);
    k2_cn<<<64, 256>>>();
    k3_pix<<<256, 256>>>(ei);
    k4_tw<<<1, 128>>>();
    k5_row<<<16384, 128>>>();
    k6_col<<<2048, 256>>>(x, out);
}